// round 5
// baseline (speedup 1.0000x reference)
#include <cuda_runtime.h>
#include <math.h>

#define B_  32
#define T_  1024
#define C_  128
#define G_  896
#define G3_ 2688
#define H_  896
#define NB  112      // persistent CTAs for the scan (1/SM guaranteed by smem)

typedef unsigned long long u64;

// ---------------- device scratch (allocation-free: __device__ globals) -------
__device__ __align__(256) float g_gx [(size_t)T_ * G3_ * B_];  // [T][3G][B]
__device__ __align__(256) float g_hs2[(size_t)T_ * G_  * B_];  // [t/2][G][B][2] (t-pair interleaved)
__device__ __align__(256) float g_h  [2 * G_ * B_];            // double-buffered h, [G][B]
__device__ unsigned g_bar_count = 0;
__device__ volatile unsigned g_bar_gen = 0;

// ---------------- packed f32x2 helpers --------------------------------------
__device__ __forceinline__ void fma2(u64 &acc, u64 a, u64 b) {
    asm("fma.rn.f32x2 %0, %1, %2, %0;" : "+l"(acc) : "l"(a), "l"(b));
}
__device__ __forceinline__ u64 pack2(float x, float y) {
    u64 r; asm("mov.b64 %0, {%1,%2};" : "=l"(r) : "f"(x), "f"(y)); return r;
}
__device__ __forceinline__ float2 unpack2(u64 v) {
    float2 r; asm("mov.b64 {%0,%1}, %2;" : "=f"(r.x), "=f"(r.y) : "l"(v)); return r;
}
__device__ __forceinline__ float sigm(float x) {
    return __fdividef(1.0f, 1.0f + __expf(-x));
}
__device__ __forceinline__ float tanh_fast(float x) {
    // tanh(x) = 1 - 2/(e^{2x}+1); exact limits at +/-inf of expf
    float e = __expf(2.0f * x);
    return 1.0f - __fdividef(2.0f, e + 1.0f);
}

// ============================================================================
// gx[t][row][b] = b_ih[row] + sum_c x[b][t][c] * w_ih[row][c]
// grid (42 row-tiles of 64, 1024 t), 128 threads.  CTA(0,0) also inits g_h.
// ============================================================================
__global__ __launch_bounds__(128) void k_gx(const float* __restrict__ x,
                                            const float* __restrict__ state,
                                            const float* __restrict__ w_ih,
                                            const float* __restrict__ b_ih) {
    __shared__ float ws[128 * 64];   // [c][r]
    __shared__ float xs[128 * 32];   // [c][b]
    const int tid = threadIdx.x;
    const int r0  = blockIdx.x * 64;
    const int t   = blockIdx.y;

    if (blockIdx.x == 0 && blockIdx.y == 0) {
        // h0[g][b] = state[0][b][g]
        for (int i = tid; i < G_ * B_; i += 128) {
            int g = i >> 5, b = i & 31;
            g_h[g * 32 + b] = state[b * G_ + g];
        }
    }

    for (int i = tid; i < 64 * 32; i += 128) {
        int r = i >> 5, cq = (i & 31) * 4;
        float4 v = *(const float4*)(w_ih + (size_t)(r0 + r) * C_ + cq);
        ws[(cq+0)*64 + r] = v.x; ws[(cq+1)*64 + r] = v.y;
        ws[(cq+2)*64 + r] = v.z; ws[(cq+3)*64 + r] = v.w;
    }
    for (int i = tid; i < 32 * 32; i += 128) {
        int b = i >> 5, cq = (i & 31) * 4;
        float4 v = *(const float4*)(x + ((size_t)b * T_ + t) * C_ + cq);
        xs[(cq+0)*32 + b] = v.x; xs[(cq+1)*32 + b] = v.y;
        xs[(cq+2)*32 + b] = v.z; xs[(cq+3)*32 + b] = v.w;
    }
    __syncthreads();

    const int rt  = tid >> 3;       // 0..15 -> 4 rows each
    const int bpt = tid & 7;        // 0..7  -> 4 b each
    const int rr  = rt * 4;
    const int bb  = bpt * 4;
    u64 acc[4][2] = {};

#pragma unroll 2
    for (int k = 0; k < 128; ++k) {
        const float* wk = ws + k * 64 + rr;
        u64 h0 = *(const u64*)(xs + k * 32 + bb);
        u64 h1 = *(const u64*)(xs + k * 32 + bb + 2);
#pragma unroll
        for (int i = 0; i < 4; ++i) {
            u64 wp = pack2(wk[i], wk[i]);
            fma2(acc[i][0], wp, h0);
            fma2(acc[i][1], wp, h1);
        }
    }
#pragma unroll
    for (int i = 0; i < 4; ++i) {
        float bias = b_ih[r0 + rr + i];
        float* op = g_gx + ((size_t)t * G3_ + r0 + rr + i) * B_ + bb;
        float2 a0 = unpack2(acc[i][0]); a0.x += bias; a0.y += bias;
        float2 a1 = unpack2(acc[i][1]); a1.x += bias; a1.y += bias;
        *(float2*)(op)     = a0;
        *(float2*)(op + 2) = a1;
    }
}

// ============================================================================
// Persistent GRU scan. 112 CTAs x 256 threads. CTA owns j in [cta*8, cta*8+8)
// as 4 j-pairs living in the f32x2 lanes. warp = ksplit (8 x 112 k).
// SMEM: hs[896][32] (114688) + ws2 float2[896][12] (86016) + red u64[8][3][4][32]
// (24576) = 225280 B -> 1 CTA/SM, 112 co-resident, grid barrier safe.
// ============================================================================
#define RNN_SMEM ((G_*B_ + 896*24 + 8*3*4*32*2) * 4)   // 225280

__global__ __launch_bounds__(256) void k_rnn(const float* __restrict__ w_hh,
                                             const float* __restrict__ b_hh) {
    extern __shared__ float sm[];
    float*  hs  = sm;                          // [896][32]
    float2* ws2 = (float2*)(sm + G_ * B_);     // [k][3 gates][4 jp] pairs (j0,j1)
    u64*    red = (u64*)(sm + G_ * B_ + 896 * 24);  // [8 warp][3 g][4 jp][32 b]

    const int tid = threadIdx.x;
    const int cta = blockIdx.x;
    const int j0  = cta * 8;

    // fill ws2 (one-time; k-contiguous global reads)
    {
        float* wsf = (float*)ws2;
        for (int lr = 0; lr < 24; ++lr) {
            int g = lr >> 3, jl = lr & 7, jp = jl >> 1, half = jl & 1;
            const float* src = w_hh + (size_t)(g * G_ + j0 + jl) * G_;
            for (int k = tid; k < G_; k += 256)
                wsf[(k * 12 + g * 4 + jp) * 2 + half] = src[k];
        }
    }

    const int warp = tid >> 5;
    const int lane = tid & 31;
    const int jp_m = lane >> 3;     // mainloop jp 0..3
    const int bq   = lane & 7;
    const int b0   = bq * 4;
    const int k0   = warp * 112;

    // epilogue coords (threads 0..127)
    const int jp_e = tid >> 5;      // 0..3 for tid<128
    const int b_e  = lane;          // 0..31
    const int je0  = j0 + 2 * jp_e, je1 = je0 + 1;

    float2 bhr2 = {0,0}, bhz2 = {0,0}, bhn2 = {0,0};
    if (tid < 128) {
        bhr2 = make_float2(b_hh[je0],          b_hh[je1]);
        bhz2 = make_float2(b_hh[G_ + je0],     b_hh[G_ + je1]);
        bhn2 = make_float2(b_hh[2*G_ + je0],   b_hh[2*G_ + je1]);
    }
    const u64 one2 = pack2(1.0f, 1.0f);

    for (int t = 0; t < T_; ++t) {
        const int cur = t & 1, nxt = cur ^ 1;
        const float* hg = g_h + cur * (G_ * B_);

        // prefetch this step's gx (used only in epilogue; hide DRAM latency)
        float pgr0 = 0, pgr1 = 0, pgz0 = 0, pgz1 = 0, pgn0 = 0, pgn1 = 0;
        if (tid < 128) {
            const float* gxp = g_gx + (size_t)t * G3_ * B_ + b_e;
            pgr0 = __ldcs(gxp + (size_t)je0 * B_);
            pgr1 = __ldcs(gxp + (size_t)je1 * B_);
            pgz0 = __ldcs(gxp + (size_t)(G_ + je0) * B_);
            pgz1 = __ldcs(gxp + (size_t)(G_ + je1) * B_);
            pgn0 = __ldcs(gxp + (size_t)(2*G_ + je0) * B_);
            pgn1 = __ldcs(gxp + (size_t)(2*G_ + je1) * B_);
        }

        // broadcast current h into smem (L2-only: other SMs wrote it)
        for (int i = tid * 4; i < G_ * B_; i += 1024) {
            float4 v = __ldcg((const float4*)(hg + i));
            *(float4*)(hs + i) = v;
        }
        __syncthreads();    // also covers one-time ws2 fill at t==0

        u64 a[3][4];
#pragma unroll
        for (int g = 0; g < 3; ++g)
#pragma unroll
            for (int i = 0; i < 4; ++i) a[g][i] = 0ull;

        const float2* pw = ws2 + (size_t)k0 * 12 + jp_m;
        const float*  ph = hs + (size_t)k0 * 32 + b0;
#pragma unroll 4
        for (int k = 0; k < 112; ++k) {
            u64 wr = *(const u64*)(pw);
            u64 wz = *(const u64*)(pw + 4);
            u64 wn = *(const u64*)(pw + 8);
            float h0v = ph[0], h1v = ph[1], h2v = ph[2], h3v = ph[3];
            u64 hd0 = pack2(h0v, h0v), hd1 = pack2(h1v, h1v);
            u64 hd2 = pack2(h2v, h2v), hd3 = pack2(h3v, h3v);
            fma2(a[0][0], wr, hd0); fma2(a[0][1], wr, hd1);
            fma2(a[0][2], wr, hd2); fma2(a[0][3], wr, hd3);
            fma2(a[1][0], wz, hd0); fma2(a[1][1], wz, hd1);
            fma2(a[1][2], wz, hd2); fma2(a[1][3], wz, hd3);
            fma2(a[2][0], wn, hd0); fma2(a[2][1], wn, hd1);
            fma2(a[2][2], wn, hd2); fma2(a[2][3], wn, hd3);
            pw += 12; ph += 32;
        }

        // per-warp partials -> smem
#pragma unroll
        for (int g = 0; g < 3; ++g)
#pragma unroll
            for (int i = 0; i < 4; ++i)
                red[((warp * 3 + g) * 4 + jp_m) * 32 + b0 + i] = a[g][i];
        __syncthreads();

        if (tid < 128) {
            u64 sr = 0, sz = 0, sn = 0;
#pragma unroll
            for (int w = 0; w < 8; ++w) {
                fma2(sr, one2, red[((w * 3 + 0) * 4 + jp_e) * 32 + b_e]);
                fma2(sz, one2, red[((w * 3 + 1) * 4 + jp_e) * 32 + b_e]);
                fma2(sn, one2, red[((w * 3 + 2) * 4 + jp_e) * 32 + b_e]);
            }
            float2 hr = unpack2(sr), hz = unpack2(sz), hn = unpack2(sn);
            float hold0 = hs[je0 * 32 + b_e], hold1 = hs[je1 * 32 + b_e];

            float r0 = sigm(pgr0 + hr.x + bhr2.x);
            float r1 = sigm(pgr1 + hr.y + bhr2.y);
            float z0 = sigm(pgz0 + hz.x + bhz2.x);
            float z1 = sigm(pgz1 + hz.y + bhz2.y);
            float n0 = tanh_fast(pgn0 + r0 * (hn.x + bhn2.x));
            float n1 = tanh_fast(pgn1 + r1 * (hn.y + bhn2.y));
            float h0n = (1.0f - z0) * n0 + z0 * hold0;
            float h1n = (1.0f - z1) * n1 + z1 * hold1;

            float* hnp = g_h + nxt * (G_ * B_);
            hnp[je0 * 32 + b_e] = h0n;
            hnp[je1 * 32 + b_e] = h1n;
            float* hop = g_hs2 + (size_t)(t >> 1) * G_ * 64;
            hop[(size_t)je0 * 64 + b_e * 2 + (t & 1)] = h0n;
            hop[(size_t)je1 * 64 + b_e * 2 + (t & 1)] = h1n;
            __threadfence();   // every writer fences (GPU scope) before arrival
        }

        // sense-reversing grid barrier (self-restoring -> replay-safe)
        __syncthreads();
        if (tid == 0) {
            unsigned old = g_bar_gen;
            if (atomicAdd(&g_bar_count, 1u) == NB - 1) {
                g_bar_count = 0;
                __threadfence();
                g_bar_gen = old + 1;
            } else {
                while (g_bar_gen == old) { }
            }
            __threadfence();
        }
        __syncthreads();
    }
}

// ============================================================================
// out[b][t][h] = relu(sum_g hs[t][g][b] * w_post[h][g] + b_post[h])
// t-pairs live in f32x2 lanes. grid (14 h-tiles, 512 t-pairs), 128 threads.
// thread tile: 4 h x 4 b x 2 t.
// ============================================================================
__global__ __launch_bounds__(128) void k_post(const float* __restrict__ w_post,
                                              const float* __restrict__ b_post,
                                              float* __restrict__ out) {
    __shared__ float wt [64 * 64];   // [k][h]     16KB
    __shared__ float ht2[64 * 64];   // [k][b*2]   16KB
    const int tid = threadIdx.x;
    const int hb  = blockIdx.x * 64;
    const int tp  = blockIdx.y;
    const int ht  = tid >> 3;        // 0..15
    const int bt  = tid & 7;         // 0..7
    const int hh  = ht * 4;
    const int b0  = bt * 4;

    u64 acc[4][4];
#pragma unroll
    for (int i = 0; i < 4; ++i)
#pragma unroll
        for (int j = 0; j < 4; ++j) acc[i][j] = 0ull;

    for (int ch = 0; ch < 14; ++ch) {
        const int g0 = ch * 64;
        for (int i = tid; i < 64 * 16; i += 128) {
            int r = i >> 4, cq = (i & 15) * 4;
            float4 v = *(const float4*)(w_post + (size_t)(hb + r) * G_ + g0 + cq);
            wt[(cq+0)*64 + r] = v.x; wt[(cq+1)*64 + r] = v.y;
            wt[(cq+2)*64 + r] = v.z; wt[(cq+3)*64 + r] = v.w;
        }
        const float* src = g_hs2 + ((size_t)tp * G_ + g0) * 64;
        for (int i = tid * 4; i < 4096; i += 512)
            *(float4*)(ht2 + i) = *(const float4*)(src + i);
        __syncthreads();

#pragma unroll 4
        for (int k = 0; k < 64; ++k) {
            float4 w4 = *(const float4*)(wt + k * 64 + hh);
            u64 wd0 = pack2(w4.x, w4.x), wd1 = pack2(w4.y, w4.y);
            u64 wd2 = pack2(w4.z, w4.z), wd3 = pack2(w4.w, w4.w);
            const u64* hp = (const u64*)(ht2 + k * 64 + b0 * 2);
            u64 h0 = hp[0], h1 = hp[1], h2 = hp[2], h3 = hp[3];
            fma2(acc[0][0], wd0, h0); fma2(acc[0][1], wd0, h1);
            fma2(acc[0][2], wd0, h2); fma2(acc[0][3], wd0, h3);
            fma2(acc[1][0], wd1, h0); fma2(acc[1][1], wd1, h1);
            fma2(acc[1][2], wd1, h2); fma2(acc[1][3], wd1, h3);
            fma2(acc[2][0], wd2, h0); fma2(acc[2][1], wd2, h1);
            fma2(acc[2][2], wd2, h2); fma2(acc[2][3], wd2, h3);
            fma2(acc[3][0], wd3, h0); fma2(acc[3][1], wd3, h1);
            fma2(acc[3][2], wd3, h2); fma2(acc[3][3], wd3, h3);
        }
        __syncthreads();
    }

    const int t0 = tp * 2, t1 = t0 + 1;
    float bi0 = b_post[hb + hh + 0], bi1 = b_post[hb + hh + 1];
    float bi2 = b_post[hb + hh + 2], bi3 = b_post[hb + hh + 3];
#pragma unroll
    for (int j = 0; j < 4; ++j) {
        int b = b0 + j;
        float2 a0 = unpack2(acc[0][j]), a1 = unpack2(acc[1][j]);
        float2 a2 = unpack2(acc[2][j]), a3 = unpack2(acc[3][j]);
        float4 o0 = make_float4(fmaxf(a0.x + bi0, 0.f), fmaxf(a1.x + bi1, 0.f),
                                fmaxf(a2.x + bi2, 0.f), fmaxf(a3.x + bi3, 0.f));
        float4 o1 = make_float4(fmaxf(a0.y + bi0, 0.f), fmaxf(a1.y + bi1, 0.f),
                                fmaxf(a2.y + bi2, 0.f), fmaxf(a3.y + bi3, 0.f));
        *(float4*)(out + ((size_t)b * T_ + t0) * H_ + hb + hh) = o0;
        *(float4*)(out + ((size_t)b * T_ + t1) * H_ + hb + hh) = o1;
    }
}

// ============================================================================
// h_last[0][b][g] = final h (buffer 0 after 1024 steps)
// ============================================================================
__global__ void k_last(float* __restrict__ out) {
    int i = blockIdx.x * blockDim.x + threadIdx.x;
    if (i < G_ * B_) {
        int b = i / G_, g = i % G_;
        out[(size_t)B_ * T_ * H_ + i] = g_h[g * 32 + b];
    }
}

// ============================================================================
extern "C" void kernel_launch(void* const* d_in, const int* in_sizes, int n_in,
                              void* d_out, int out_size) {
    const float* x      = (const float*)d_in[0];
    const float* state  = (const float*)d_in[1];
    const float* w_ih   = (const float*)d_in[2];
    const float* w_hh   = (const float*)d_in[3];
    const float* b_ih   = (const float*)d_in[4];
    const float* b_hh   = (const float*)d_in[5];
    const float* w_post = (const float*)d_in[6];
    const float* b_post = (const float*)d_in[7];
    float* out = (float*)d_out;

    static int smem_set = 0;
    if (!smem_set) {
        cudaFuncSetAttribute(k_rnn, cudaFuncAttributeMaxDynamicSharedMemorySize, RNN_SMEM);
        smem_set = 1;
    }

    // exactly 4 launches per call -> ncu -s 5 -c 1 lands on k_rnn
    k_gx  <<<dim3(42, 1024), 128>>>(x, state, w_ih, b_ih);
    k_rnn <<<NB, 256, RNN_SMEM>>>(w_hh, b_hh);
    k_post<<<dim3(14, 512), 128>>>(w_post, b_post, out);
    k_last<<<112, 256>>>(out);
}

// round 6
// speedup vs baseline: 1.0918x; 1.0918x over previous
#include <cuda_runtime.h>
#include <math.h>

#define B_  32
#define T_  1024
#define C_  128
#define G_  896
#define G3_ 2688
#define H_  896
#define NB  112      // persistent CTAs for the scan (1/SM guaranteed by smem)

typedef unsigned long long u64;

// ---------------- device scratch (allocation-free: __device__ globals) -------
__device__ __align__(256) float g_gx[(size_t)T_ * G3_ * B_];   // [T][3G][B]
__device__ __align__(256) float g_hs[(size_t)T_ * G_  * B_];   // [T][G][B]
__device__ __align__(256) float g_h [2 * G_ * B_];             // double-buffered h, [G][B]
__device__ unsigned g_bar_count = 0;            // self-restoring barrier state
__device__ volatile unsigned g_bar_gen = 0;

// ---------------- packed f32x2 helpers --------------------------------------
__device__ __forceinline__ void fma2(u64 &acc, u64 a, u64 b) {
    asm("fma.rn.f32x2 %0, %1, %2, %0;" : "+l"(acc) : "l"(a), "l"(b));
}
__device__ __forceinline__ u64 pack2(float x, float y) {
    u64 r; asm("mov.b64 %0, {%1,%2};" : "=l"(r) : "f"(x), "f"(y)); return r;
}
__device__ __forceinline__ float2 unpack2(u64 v) {
    float2 r; asm("mov.b64 {%0,%1}, %2;" : "=f"(r.x), "=f"(r.y) : "l"(v)); return r;
}
__device__ __forceinline__ float sigm(float x) {
    return __fdividef(1.0f, 1.0f + __expf(-x));
}
__device__ __forceinline__ float tanh_fast(float x) {
    float e = __expf(2.0f * x);
    return 1.0f - __fdividef(2.0f, e + 1.0f);
}

// ============================================================================
// no-op filler so ncu's captured launch (4th) lands on k_rnn
// ============================================================================
__global__ void k_nop() {}

// ============================================================================
// gx[t][row][b] = b_ih[row] + sum_c x[b][t][c] * w_ih[row][c]
// grid (42 row-tiles of 64, 1024 t), 128 threads.  CTA(0,0) also inits g_h.
// ============================================================================
__global__ __launch_bounds__(128) void k_gx(const float* __restrict__ x,
                                            const float* __restrict__ state,
                                            const float* __restrict__ w_ih,
                                            const float* __restrict__ b_ih) {
    __shared__ float ws[128 * 64];   // [c][r]
    __shared__ float xs[128 * 32];   // [c][b]
    const int tid = threadIdx.x;
    const int r0  = blockIdx.x * 64;
    const int t   = blockIdx.y;

    if (blockIdx.x == 0 && blockIdx.y == 0) {
        for (int i = tid; i < G_ * B_; i += 128) {
            int g = i >> 5, b = i & 31;
            g_h[g * 32 + b] = state[b * G_ + g];
        }
    }

    for (int i = tid; i < 64 * 32; i += 128) {
        int r = i >> 5, cq = (i & 31) * 4;
        float4 v = *(const float4*)(w_ih + (size_t)(r0 + r) * C_ + cq);
        ws[(cq+0)*64 + r] = v.x; ws[(cq+1)*64 + r] = v.y;
        ws[(cq+2)*64 + r] = v.z; ws[(cq+3)*64 + r] = v.w;
    }
    for (int i = tid; i < 32 * 32; i += 128) {
        int b = i >> 5, cq = (i & 31) * 4;
        float4 v = *(const float4*)(x + ((size_t)b * T_ + t) * C_ + cq);
        xs[(cq+0)*32 + b] = v.x; xs[(cq+1)*32 + b] = v.y;
        xs[(cq+2)*32 + b] = v.z; xs[(cq+3)*32 + b] = v.w;
    }
    __syncthreads();

    const int rt  = tid >> 3;       // 0..15 -> 4 rows each
    const int bpt = tid & 7;        // 0..7  -> 4 b each
    const int rr  = rt * 4;
    const int bb  = bpt * 4;
    u64 acc[4][2] = {};

#pragma unroll 2
    for (int k = 0; k < 128; ++k) {
        const float* wk = ws + k * 64 + rr;
        u64 h0 = *(const u64*)(xs + k * 32 + bb);
        u64 h1 = *(const u64*)(xs + k * 32 + bb + 2);
#pragma unroll
        for (int i = 0; i < 4; ++i) {
            u64 wp = pack2(wk[i], wk[i]);
            fma2(acc[i][0], wp, h0);
            fma2(acc[i][1], wp, h1);
        }
    }
#pragma unroll
    for (int i = 0; i < 4; ++i) {
        float bias = b_ih[r0 + rr + i];
        float* op = g_gx + ((size_t)t * G3_ + r0 + rr + i) * B_ + bb;
        float2 a0 = unpack2(acc[i][0]); a0.x += bias; a0.y += bias;
        float2 a1 = unpack2(acc[i][1]); a1.x += bias; a1.y += bias;
        *(float2*)(op)     = a0;
        *(float2*)(op + 2) = a1;
    }
}

// ============================================================================
// Persistent GRU scan. 112 CTAs x 256 threads. CTA owns j in [cta*8, cta*8+8).
// SMEM: hs[896][32] (114688B) + ws[896][24] (86016B) + red (9216B) = 209920B
// -> 1 CTA/SM, 112 co-resident in wave 1, grid barrier safe.
// ============================================================================
#define RNN_SMEM ((G_*B_ + 896*24 + 3*64*12) * 4)

__global__ __launch_bounds__(256) void k_rnn(const float* __restrict__ w_hh,
                                             const float* __restrict__ b_hh) {
    extern __shared__ float sm[];
    float* hs  = sm;                  // [896][32]  current h
    float* ws  = sm + G_ * B_;        // [896][24]  k-major w_hh slice
    float* red = ws + 896 * 24;       // [3][64][12] k-split reduction

    const int tid = threadIdx.x;
    const int cta = blockIdx.x;
    const int j0  = cta * 8;

    // load this CTA's 24 w_hh rows, transposed to k-major (one-time cost)
    for (int lr = 0; lr < 24; ++lr) {
        int gate = lr >> 3, jl = lr & 7;
        const float* src = w_hh + (size_t)(gate * G_ + j0 + jl) * G_;
        for (int k = tid; k < G_; k += 256) ws[k * 24 + lr] = src[k];
    }

    const int ksplit = tid >> 6;      // 0..3, 224 k each
    const int tile   = tid & 63;
    const int jl     = tile >> 3;     // 0..7
    const int bpt    = tile & 7;      // 0..7
    const int bb     = bpt * 4;
    const int jg     = j0 + jl;

    float bhr = 0.f, bhz = 0.f, bhn = 0.f;
    if (tid < 64) {
        bhr = b_hh[jg];
        bhz = b_hh[G_ + jg];
        bhn = b_hh[2 * G_ + jg];
    }

    for (int t = 0; t < T_; ++t) {
        const int cur = t & 1, nxt = cur ^ 1;
        const float* hg = g_h + cur * (G_ * B_);

        // prefetch this step's gx early (epilogue-only data): hide latency
        // under the h broadcast + mainloop instead of exposing it serially.
        float2 pgr[2], pgz[2], pgn[2];
        if (tid < 64) {
            const float* gxp = g_gx + (size_t)t * G3_ * B_;
#pragma unroll
            for (int p = 0; p < 2; ++p) {
                int bo = bb + 2 * p;
                pgr[p] = __ldcs((const float2*)(gxp + (size_t)(jg) * B_ + bo));
                pgz[p] = __ldcs((const float2*)(gxp + (size_t)(G_ + jg) * B_ + bo));
                pgn[p] = __ldcs((const float2*)(gxp + (size_t)(2 * G_ + jg) * B_ + bo));
            }
        }

        // pull current h into SMEM (L2-only loads: other SMs wrote it)
        for (int i = tid * 4; i < G_ * B_; i += 1024) {
            float4 v = __ldcg((const float4*)(hg + i));
            *(float4*)(hs + i) = v;
        }
        __syncthreads();   // also covers the one-time ws load at t==0

        u64 a[3][2] = {};
        const int k0 = ksplit * 224;
#pragma unroll 4
        for (int k = k0; k < k0 + 224; ++k) {
            const float* wk = ws + k * 24 + jl;
            u64 h0 = *(const u64*)(hs + k * 32 + bb);
            u64 h1 = *(const u64*)(hs + k * 32 + bb + 2);
            u64 wr = pack2(wk[0],  wk[0]);
            u64 wz = pack2(wk[8],  wk[8]);
            u64 wn = pack2(wk[16], wk[16]);
            fma2(a[0][0], wr, h0); fma2(a[0][1], wr, h1);
            fma2(a[1][0], wz, h0); fma2(a[1][1], wz, h1);
            fma2(a[2][0], wn, h0); fma2(a[2][1], wn, h1);
        }

        // k-split reduction via smem
        if (ksplit) {
            float2* rp = (float2*)red + ((ksplit - 1) * 64 + tile) * 6;
#pragma unroll
            for (int g = 0; g < 3; ++g) {
                rp[g * 2]     = unpack2(a[g][0]);
                rp[g * 2 + 1] = unpack2(a[g][1]);
            }
        }
        __syncthreads();

        if (tid < 64) {
            float2 av[3][2];
#pragma unroll
            for (int g = 0; g < 3; ++g) {
                av[g][0] = unpack2(a[g][0]);
                av[g][1] = unpack2(a[g][1]);
            }
#pragma unroll
            for (int s = 0; s < 3; ++s) {
                float2* rp = (float2*)red + (s * 64 + tile) * 6;
#pragma unroll
                for (int g = 0; g < 3; ++g) {
                    float2 v0 = rp[g * 2], v1 = rp[g * 2 + 1];
                    av[g][0].x += v0.x; av[g][0].y += v0.y;
                    av[g][1].x += v1.x; av[g][1].y += v1.y;
                }
            }
            float* hn = g_h  + nxt * (G_ * B_);
            float* ho = g_hs + (size_t)t * G_ * B_;
#pragma unroll
            for (int p = 0; p < 2; ++p) {
                int bo = bb + 2 * p;
                float2 hold = *(const float2*)(hs + jg * 32 + bo);

                float rx = sigm(pgr[p].x + av[0][p].x + bhr);
                float ry = sigm(pgr[p].y + av[0][p].y + bhr);
                float zx = sigm(pgz[p].x + av[1][p].x + bhz);
                float zy = sigm(pgz[p].y + av[1][p].y + bhz);
                float nx = tanh_fast(pgn[p].x + rx * (av[2][p].x + bhn));
                float ny = tanh_fast(pgn[p].y + ry * (av[2][p].y + bhn));
                float hx = (1.f - zx) * nx + zx * hold.x;
                float hy = (1.f - zy) * ny + zy * hold.y;

                float2 hv = make_float2(hx, hy);
                *(float2*)(hn + jg * 32 + bo) = hv;
                *(float2*)(ho + jg * 32 + bo) = hv;
            }
            __threadfence();   // writers fence before barrier arrival
        }

        // sense-reversing grid barrier (self-restoring -> replay-safe)
        __syncthreads();
        if (tid == 0) {
            unsigned old = g_bar_gen;
            if (atomicAdd(&g_bar_count, 1u) == NB - 1) {
                g_bar_count = 0;
                __threadfence();
                g_bar_gen = old + 1;
            } else {
                while (g_bar_gen == old) { __nanosleep(32); }
            }
            __threadfence();
        }
        __syncthreads();
    }
}

// ============================================================================
// out[b][t][h] = relu(sum_g hs[t][g][b] * w_post[h][g] + b_post[h])
// grid (14 h-tiles of 64, 1024 t), 128 threads
// ============================================================================
__global__ __launch_bounds__(128) void k_post(const float* __restrict__ w_post,
                                              const float* __restrict__ b_post,
                                              float* __restrict__ out) {
    __shared__ float wsc[128 * 64];  // [g_chunk][h]
    __shared__ float hsc[128 * 32];  // [g_chunk][b]
    const int tid = threadIdx.x;
    const int h0  = blockIdx.x * 64;
    const int t   = blockIdx.y;
    const int rt  = tid >> 3, bpt = tid & 7;
    const int rr  = rt * 4,   bb  = bpt * 4;
    u64 acc[4][2] = {};

    for (int ch = 0; ch < 7; ++ch) {
        const int g0 = ch * 128;
        for (int i = tid; i < 64 * 32; i += 128) {
            int r = i >> 5, cq = (i & 31) * 4;
            float4 v = *(const float4*)(w_post + (size_t)(h0 + r) * G_ + g0 + cq);
            wsc[(cq+0)*64 + r] = v.x; wsc[(cq+1)*64 + r] = v.y;
            wsc[(cq+2)*64 + r] = v.z; wsc[(cq+3)*64 + r] = v.w;
        }
        for (int i = tid; i < 1024; i += 128) {
            float4 v = *(const float4*)(g_hs + ((size_t)t * G_ + g0) * B_ + i * 4);
            *(float4*)(hsc + i * 4) = v;
        }
        __syncthreads();
#pragma unroll 2
        for (int k = 0; k < 128; ++k) {
            const float* wk = wsc + k * 64 + rr;
            u64 h0v = *(const u64*)(hsc + k * 32 + bb);
            u64 h1v = *(const u64*)(hsc + k * 32 + bb + 2);
#pragma unroll
            for (int i = 0; i < 4; ++i) {
                u64 wp = pack2(wk[i], wk[i]);
                fma2(acc[i][0], wp, h0v);
                fma2(acc[i][1], wp, h1v);
            }
        }
        __syncthreads();
    }

    float bias[4], vv[4][4];
#pragma unroll
    for (int i = 0; i < 4; ++i) bias[i] = b_post[h0 + rr + i];
#pragma unroll
    for (int i = 0; i < 4; ++i) {
        float2 a0 = unpack2(acc[i][0]), a1 = unpack2(acc[i][1]);
        vv[i][0] = fmaxf(a0.x + bias[i], 0.f);
        vv[i][1] = fmaxf(a0.y + bias[i], 0.f);
        vv[i][2] = fmaxf(a1.x + bias[i], 0.f);
        vv[i][3] = fmaxf(a1.y + bias[i], 0.f);
    }
#pragma unroll
    for (int bl = 0; bl < 4; ++bl) {
        int b = bb + bl;
        float4 o = make_float4(vv[0][bl], vv[1][bl], vv[2][bl], vv[3][bl]);
        *(float4*)(out + ((size_t)b * T_ + t) * H_ + h0 + rr) = o;
    }
}

// ============================================================================
// h_last[0][b][g] = final h (buffer 0 after 1024 steps)
// ============================================================================
__global__ void k_last(float* __restrict__ out) {
    int i = blockIdx.x * blockDim.x + threadIdx.x;
    if (i < G_ * B_) {
        int b = i / G_, g = i % G_;
        out[(size_t)B_ * T_ * H_ + i] = g_h[g * 32 + b];
    }
}

// ============================================================================
extern "C" void kernel_launch(void* const* d_in, const int* in_sizes, int n_in,
                              void* d_out, int out_size) {
    const float* x      = (const float*)d_in[0];
    const float* state  = (const float*)d_in[1];
    const float* w_ih   = (const float*)d_in[2];
    const float* w_hh   = (const float*)d_in[3];
    const float* b_ih   = (const float*)d_in[4];
    const float* b_hh   = (const float*)d_in[5];
    const float* w_post = (const float*)d_in[6];
    const float* b_post = (const float*)d_in[7];
    float* out = (float*)d_out;

    static int smem_set = 0;
    if (!smem_set) {
        cudaFuncSetAttribute(k_rnn, cudaFuncAttributeMaxDynamicSharedMemorySize, RNN_SMEM);
        smem_set = 1;
    }

    // k_rnn is the 4th launch: empirically ncu captures launch #4.
    k_gx  <<<dim3(42, 1024), 128>>>(x, state, w_ih, b_ih);
    k_nop <<<1, 32>>>();
    k_nop <<<1, 32>>>();
    k_rnn <<<NB, 256, RNN_SMEM>>>(w_hh, b_hh);
    k_post<<<dim3(14, 1024), 128>>>(w_post, b_post, out);
    k_last<<<112, 256>>>(out);
}

// round 7
// speedup vs baseline: 1.6261x; 1.4894x over previous
#include <cuda_runtime.h>
#include <math.h>

#define B_  32
#define T_  1024
#define C_  128
#define G_  896
#define G3_ 2688
#define H_  896
#define NB  112      // persistent CTAs for the scan (1/SM guaranteed by smem)

typedef unsigned long long u64;

// ---------------- device scratch (allocation-free: __device__ globals) -------
__device__ __align__(256) float g_gx [(size_t)T_ * G3_ * B_];  // [T][3G][B]
__device__ __align__(256) float g_hs2[(size_t)T_ * G_  * B_];  // [t/2][G][B][2]
__device__ __align__(256) float g_h  [2 * G_ * B_];            // double-buffered h, [G][B]
__device__ unsigned g_bar_count = 0;
__device__ volatile unsigned g_bar_gen = 0;

// ---------------- helpers ----------------------------------------------------
__device__ __forceinline__ void fma2(u64 &acc, u64 a, u64 b) {
    asm("fma.rn.f32x2 %0, %1, %2, %0;" : "+l"(acc) : "l"(a), "l"(b));
}
__device__ __forceinline__ u64 pack2(float x, float y) {
    u64 r; asm("mov.b64 %0, {%1,%2};" : "=l"(r) : "f"(x), "f"(y)); return r;
}
__device__ __forceinline__ float2 unpack2(u64 v) {
    float2 r; asm("mov.b64 {%0,%1}, %2;" : "=f"(r.x), "=f"(r.y) : "l"(v)); return r;
}
__device__ __forceinline__ float sigm(float x) {
    return __fdividef(1.0f, 1.0f + __expf(-x));
}
__device__ __forceinline__ float tanh_fast(float x) {
    float e = __expf(2.0f * x);
    return 1.0f - __fdividef(2.0f, e + 1.0f);
}
__device__ __forceinline__ void cp_async16(float* smem_dst, const float* gsrc) {
    unsigned s = (unsigned)__cvta_generic_to_shared(smem_dst);
    asm volatile("cp.async.cg.shared.global [%0], [%1], 16;" :: "r"(s), "l"(gsrc));
}
#define CP_COMMIT() asm volatile("cp.async.commit_group;")
#define CP_WAIT(n)  asm volatile("cp.async.wait_group %0;" :: "n"(n))

// ============================================================================
__global__ void k_nop() {}

// ============================================================================
// gx[t][row][b] = b_ih[row] + sum_c x[b][t][c] * w_ih[row][c]
// ============================================================================
__global__ __launch_bounds__(128) void k_gx(const float* __restrict__ x,
                                            const float* __restrict__ state,
                                            const float* __restrict__ w_ih,
                                            const float* __restrict__ b_ih) {
    __shared__ float ws[128 * 64];   // [c][r]
    __shared__ float xs[128 * 32];   // [c][b]
    const int tid = threadIdx.x;
    const int r0  = blockIdx.x * 64;
    const int t   = blockIdx.y;

    if (blockIdx.x == 0 && blockIdx.y == 0) {
        for (int i = tid; i < G_ * B_; i += 128) {
            int g = i >> 5, b = i & 31;
            g_h[g * 32 + b] = state[b * G_ + g];
        }
    }

    for (int i = tid; i < 64 * 32; i += 128) {
        int r = i >> 5, cq = (i & 31) * 4;
        float4 v = *(const float4*)(w_ih + (size_t)(r0 + r) * C_ + cq);
        ws[(cq+0)*64 + r] = v.x; ws[(cq+1)*64 + r] = v.y;
        ws[(cq+2)*64 + r] = v.z; ws[(cq+3)*64 + r] = v.w;
    }
    for (int i = tid; i < 32 * 32; i += 128) {
        int b = i >> 5, cq = (i & 31) * 4;
        float4 v = *(const float4*)(x + ((size_t)b * T_ + t) * C_ + cq);
        xs[(cq+0)*32 + b] = v.x; xs[(cq+1)*32 + b] = v.y;
        xs[(cq+2)*32 + b] = v.z; xs[(cq+3)*32 + b] = v.w;
    }
    __syncthreads();

    const int rt  = tid >> 3;
    const int bpt = tid & 7;
    const int rr  = rt * 4;
    const int bb  = bpt * 4;
    u64 acc[4][2] = {};

#pragma unroll 2
    for (int k = 0; k < 128; ++k) {
        const float* wk = ws + k * 64 + rr;
        u64 h0 = *(const u64*)(xs + k * 32 + bb);
        u64 h1 = *(const u64*)(xs + k * 32 + bb + 2);
#pragma unroll
        for (int i = 0; i < 4; ++i) {
            u64 wp = pack2(wk[i], wk[i]);
            fma2(acc[i][0], wp, h0);
            fma2(acc[i][1], wp, h1);
        }
    }
#pragma unroll
    for (int i = 0; i < 4; ++i) {
        float bias = b_ih[r0 + rr + i];
        float* op = g_gx + ((size_t)t * G3_ + r0 + rr + i) * B_ + bb;
        float2 a0 = unpack2(acc[i][0]); a0.x += bias; a0.y += bias;
        float2 a1 = unpack2(acc[i][1]); a1.x += bias; a1.y += bias;
        *(float2*)(op)     = a0;
        *(float2*)(op + 2) = a1;
    }
}

// ============================================================================
// Persistent GRU scan, 112 CTAs x 256 threads (8 warps).
// Warp w owns k-slice [w*112, w*112+112): cp.asyncs its own h slice (no block
// sync between load and compute). Lane = (jl 0..7, bq 0..3): 1 j x 8 b x 3
// gates, b-pairs in the f32x2 lanes. 8-way k-split; partials in smem; epilogue
// on all 256 threads (thread = one (j,b) output).
// SMEM: hs 114688 + ws 86016 + red 24576 = 225280 B -> 1 CTA/SM.
// ============================================================================
#define RNN_SMEM ((G_*B_ + 896*24 + 8*3*8*16*2) * 4)   // 225280

__global__ __launch_bounds__(256) void k_rnn(const float* __restrict__ w_hh,
                                             const float* __restrict__ b_hh) {
    extern __shared__ float sm[];
    float* hs   = sm;                         // [896][32]
    float* ws   = sm + G_ * B_;               // [896][24]  ws[k][g*8+j]
    u64*   redp = (u64*)(ws + 896 * 24);      // [8 w][3 g][8 j][16 bp]
    float* redf = (float*)redp;               // same, as [8][3][8][32] floats

    const int tid  = threadIdx.x;
    const int warp = tid >> 5;
    const int lane = tid & 31;
    const int cta  = blockIdx.x;
    const int j0   = cta * 8;
    const int k0   = warp * 112;

    // one-time: ws[k][g*8+j] = w_hh[g*G + j0+j][k]
    for (int row = 0; row < 24; ++row) {
        const float* src = w_hh + ((size_t)(row >> 3) * G_ + j0 + (row & 7)) * G_;
        for (int k = tid; k < G_; k += 256) ws[k * 24 + row] = src[k];
    }
    __syncthreads();

    // mainloop coords
    const int jl = lane >> 2;        // 0..7
    const int bq = lane & 3;         // 0..3 -> b0 = bq*8
    const int b0 = bq * 8;

    // epilogue coords: thread = (j = warp, b = lane)
    const int je  = j0 + warp;
    const float bhr = b_hh[je];
    const float bhz = b_hh[G_  + je];
    const float bhn = b_hh[2*G_ + je];

    for (int t = 0; t < T_; ++t) {
        const int cur = t & 1, nxt = cur ^ 1;
        const float* hg = g_h + cur * (G_ * B_);

        // epilogue prefetch (hidden under h-copy + mainloop)
        const float* gxp = g_gx + (size_t)t * G3_ * B_ + lane;
        float pgr   = __ldcs(gxp + (size_t)je * B_);
        float pgz   = __ldcs(gxp + (size_t)(G_ + je) * B_);
        float pgn   = __ldcs(gxp + (size_t)(2 * G_ + je) * B_);
        float phold = __ldcg(hg + je * 32 + lane);

        // warp-private h slice: 3584 floats via cp.async.cg, 2 groups of 56 rows
        {
            const float* src = hg + k0 * 32;
            float* dst = hs + k0 * 32;
#pragma unroll
            for (int i = 0; i < 14; ++i)
                cp_async16(dst + (i * 32 + lane) * 4, src + (i * 32 + lane) * 4);
            CP_COMMIT();
#pragma unroll
            for (int i = 14; i < 28; ++i)
                cp_async16(dst + (i * 32 + lane) * 4, src + (i * 32 + lane) * 4);
            CP_COMMIT();
        }

        u64 ar[4] = {}, az[4] = {}, an[4] = {};

        CP_WAIT(1);          // group A (rows k0..k0+55) ready
        __syncwarp();
        {
            const float* wp = ws + (size_t)k0 * 24 + jl;
            const u64*   hp = (const u64*)(hs + (size_t)k0 * 32 + b0);
#pragma unroll 4
            for (int k = 0; k < 56; ++k) {
                float wr = wp[0], wz = wp[8], wn = wp[16];
                u64 h0 = hp[0], h1 = hp[1], h2 = hp[2], h3 = hp[3];
                u64 wrd = pack2(wr, wr), wzd = pack2(wz, wz), wnd = pack2(wn, wn);
                fma2(ar[0], wrd, h0); fma2(ar[1], wrd, h1);
                fma2(ar[2], wrd, h2); fma2(ar[3], wrd, h3);
                fma2(az[0], wzd, h0); fma2(az[1], wzd, h1);
                fma2(az[2], wzd, h2); fma2(az[3], wzd, h3);
                fma2(an[0], wnd, h0); fma2(an[1], wnd, h1);
                fma2(an[2], wnd, h2); fma2(an[3], wnd, h3);
                wp += 24; hp += 16;
            }
        }
        CP_WAIT(0);          // group B ready
        __syncwarp();
        {
            const float* wp = ws + (size_t)(k0 + 56) * 24 + jl;
            const u64*   hp = (const u64*)(hs + (size_t)(k0 + 56) * 32 + b0);
#pragma unroll 4
            for (int k = 0; k < 56; ++k) {
                float wr = wp[0], wz = wp[8], wn = wp[16];
                u64 h0 = hp[0], h1 = hp[1], h2 = hp[2], h3 = hp[3];
                u64 wrd = pack2(wr, wr), wzd = pack2(wz, wz), wnd = pack2(wn, wn);
                fma2(ar[0], wrd, h0); fma2(ar[1], wrd, h1);
                fma2(ar[2], wrd, h2); fma2(ar[3], wrd, h3);
                fma2(az[0], wzd, h0); fma2(az[1], wzd, h1);
                fma2(az[2], wzd, h2); fma2(az[3], wzd, h3);
                fma2(an[0], wnd, h0); fma2(an[1], wnd, h1);
                fma2(an[2], wnd, h2); fma2(an[3], wnd, h3);
                wp += 24; hp += 16;
            }
        }

        // partials -> smem: red[w][g][jl][bp], u64 covers b-pair
        {
            u64* rp = redp + (((size_t)warp * 3 * 8 + jl) * 16) + bq * 4;
#pragma unroll
            for (int i = 0; i < 4; ++i) rp[i]           = ar[i];
#pragma unroll
            for (int i = 0; i < 4; ++i) rp[8 * 16 + i]  = az[i];
#pragma unroll
            for (int i = 0; i < 4; ++i) rp[16 * 16 + i] = an[i];
        }
        __syncthreads();

        // epilogue: thread (j = warp, b = lane); partial reads are stride-1
        {
            float sr = 0.f, sz = 0.f, sn = 0.f;
#pragma unroll
            for (int w = 0; w < 8; ++w) {
                const float* rf = redf + (((size_t)w * 3 * 8 + warp) * 32) + lane;
                sr += rf[0];
                sz += rf[8 * 32];
                sn += rf[16 * 32];
            }
            float r = sigm(pgr + sr + bhr);
            float z = sigm(pgz + sz + bhz);
            float n = tanh_fast(pgn + r * (sn + bhn));
            float h = (1.0f - z) * n + z * phold;

            g_h[nxt * (G_ * B_) + je * 32 + lane] = h;
            g_hs2[(size_t)(t >> 1) * G_ * 64 + (size_t)je * 64 + lane * 2 + (t & 1)] = h;
            __threadfence();    // every writer: h visible before barrier arrival
        }

        // sense-reversing grid barrier (self-restoring -> replay-safe)
        __syncthreads();
        if (tid == 0) {
            unsigned old = g_bar_gen;
            if (atomicAdd(&g_bar_count, 1u) == NB - 1) {
                g_bar_count = 0;
                __threadfence();
                g_bar_gen = old + 1;
            } else {
                while (g_bar_gen == old) { __nanosleep(32); }
            }
            __threadfence();
        }
        __syncthreads();
    }
}

// ============================================================================
// out[b][t][h] = relu(sum_g hs[t][g][b] * w_post[h][g] + b_post[h])
// t-pairs in f32x2 lanes. grid (14 h-tiles, 512 t-pairs), 128 threads.
// (validated in round 4's passing run)
// ============================================================================
__global__ __launch_bounds__(128) void k_post(const float* __restrict__ w_post,
                                              const float* __restrict__ b_post,
                                              float* __restrict__ out) {
    __shared__ float wt [64 * 64];   // [k][h]
    __shared__ float ht2[64 * 64];   // [k][b*2]
    const int tid = threadIdx.x;
    const int hb  = blockIdx.x * 64;
    const int tp  = blockIdx.y;
    const int ht  = tid >> 3;
    const int bt  = tid & 7;
    const int hh  = ht * 4;
    const int b0  = bt * 4;

    u64 acc[4][4];
#pragma unroll
    for (int i = 0; i < 4; ++i)
#pragma unroll
        for (int j = 0; j < 4; ++j) acc[i][j] = 0ull;

    for (int ch = 0; ch < 14; ++ch) {
        const int g0 = ch * 64;
        for (int i = tid; i < 64 * 16; i += 128) {
            int r = i >> 4, cq = (i & 15) * 4;
            float4 v = *(const float4*)(w_post + (size_t)(hb + r) * G_ + g0 + cq);
            wt[(cq+0)*64 + r] = v.x; wt[(cq+1)*64 + r] = v.y;
            wt[(cq+2)*64 + r] = v.z; wt[(cq+3)*64 + r] = v.w;
        }
        const float* src = g_hs2 + ((size_t)tp * G_ + g0) * 64;
        for (int i = tid * 4; i < 4096; i += 512)
            *(float4*)(ht2 + i) = *(const float4*)(src + i);
        __syncthreads();

#pragma unroll 4
        for (int k = 0; k < 64; ++k) {
            float4 w4 = *(const float4*)(wt + k * 64 + hh);
            u64 wd0 = pack2(w4.x, w4.x), wd1 = pack2(w4.y, w4.y);
            u64 wd2 = pack2(w4.z, w4.z), wd3 = pack2(w4.w, w4.w);
            const u64* hp = (const u64*)(ht2 + k * 64 + b0 * 2);
            u64 h0 = hp[0], h1 = hp[1], h2 = hp[2], h3 = hp[3];
            fma2(acc[0][0], wd0, h0); fma2(acc[0][1], wd0, h1);
            fma2(acc[0][2], wd0, h2); fma2(acc[0][3], wd0, h3);
            fma2(acc[1][0], wd1, h0); fma2(acc[1][1], wd1, h1);
            fma2(acc[1][2], wd1, h2); fma2(acc[1][3], wd1, h3);
            fma2(acc[2][0], wd2, h0); fma2(acc[2][1], wd2, h1);
            fma2(acc[2][2], wd2, h2); fma2(acc[2][3], wd2, h3);
            fma2(acc[3][0], wd3, h0); fma2(acc[3][1], wd3, h1);
            fma2(acc[3][2], wd3, h2); fma2(acc[3][3], wd3, h3);
        }
        __syncthreads();
    }

    const int t0 = tp * 2, t1 = t0 + 1;
    float bi0 = b_post[hb + hh + 0], bi1 = b_post[hb + hh + 1];
    float bi2 = b_post[hb + hh + 2], bi3 = b_post[hb + hh + 3];
#pragma unroll
    for (int j = 0; j < 4; ++j) {
        int b = b0 + j;
        float2 a0 = unpack2(acc[0][j]), a1 = unpack2(acc[1][j]);
        float2 a2 = unpack2(acc[2][j]), a3 = unpack2(acc[3][j]);
        float4 o0 = make_float4(fmaxf(a0.x + bi0, 0.f), fmaxf(a1.x + bi1, 0.f),
                                fmaxf(a2.x + bi2, 0.f), fmaxf(a3.x + bi3, 0.f));
        float4 o1 = make_float4(fmaxf(a0.y + bi0, 0.f), fmaxf(a1.y + bi1, 0.f),
                                fmaxf(a2.y + bi2, 0.f), fmaxf(a3.y + bi3, 0.f));
        *(float4*)(out + ((size_t)b * T_ + t0) * H_ + hb + hh) = o0;
        *(float4*)(out + ((size_t)b * T_ + t1) * H_ + hb + hh) = o1;
    }
}

// ============================================================================
__global__ void k_last(float* __restrict__ out) {
    int i = blockIdx.x * blockDim.x + threadIdx.x;
    if (i < G_ * B_) {
        int b = i / G_, g = i % G_;
        out[(size_t)B_ * T_ * H_ + i] = g_h[g * 32 + b];
    }
}

// ============================================================================
extern "C" void kernel_launch(void* const* d_in, const int* in_sizes, int n_in,
                              void* d_out, int out_size) {
    const float* x      = (const float*)d_in[0];
    const float* state  = (const float*)d_in[1];
    const float* w_ih   = (const float*)d_in[2];
    const float* w_hh   = (const float*)d_in[3];
    const float* b_ih   = (const float*)d_in[4];
    const float* b_hh   = (const float*)d_in[5];
    const float* w_post = (const float*)d_in[6];
    const float* b_post = (const float*)d_in[7];
    float* out = (float*)d_out;

    static int smem_set = 0;
    if (!smem_set) {
        cudaFuncSetAttribute(k_rnn, cudaFuncAttributeMaxDynamicSharedMemorySize, RNN_SMEM);
        smem_set = 1;
    }

    // k_rnn is the 4th launch: ncu captures launch #4.
    k_gx  <<<dim3(42, 1024), 128>>>(x, state, w_ih, b_ih);
    k_nop <<<1, 32>>>();
    k_nop <<<1, 32>>>();
    k_rnn <<<NB, 256, RNN_SMEM>>>(w_hh, b_hh);
    k_post<<<dim3(14, 512), 128>>>(w_post, b_post, out);
    k_last<<<112, 256>>>(out);
}